// round 1
// baseline (speedup 1.0000x reference)
#include <cuda_runtime.h>
#include <cuda_bf16.h>
#include <cstdint>

#define B_ROWS 8192
#define DDIM 768
#define NLAB 7
#define TEMP 0.3f
#define LAM 0.9f

#define BM 128
#define BN 128
#define BK 64
#define PAD_K 72      // bf16 elements per smem row (144B stride -> conflict-free ldmatrix)
#define SS_LD 65      // float stride for 64-col staging buffer
#define NSPLIT 2      // column splits of the contrast GEMM

// ---------------- scratch (static device memory; no allocations) ----------------
__device__ __nv_bfloat16 g_en[B_ROWS * DDIM];
__device__ float g_m[NSPLIT * B_ROWS];
__device__ float g_s[NSPLIT * B_ROWS];
__device__ float g_p[NSPLIT * B_ROWS];
__device__ float g_ce[B_ROWS];
__device__ int   g_cnt[NLAB];

// ---------------- helpers ----------------
__device__ __forceinline__ void ldsm_x4(uint32_t* r, const void* p) {
    uint32_t addr = (uint32_t)__cvta_generic_to_shared(p);
    asm volatile("ldmatrix.sync.aligned.m8n8.x4.shared.b16 {%0,%1,%2,%3}, [%4];"
                 : "=r"(r[0]), "=r"(r[1]), "=r"(r[2]), "=r"(r[3]) : "r"(addr));
}

__device__ __forceinline__ void mma_bf16(float* c, const uint32_t* a, const uint32_t* b) {
    asm volatile(
        "mma.sync.aligned.m16n8k16.row.col.f32.bf16.bf16.f32 "
        "{%0,%1,%2,%3}, {%4,%5,%6,%7}, {%8,%9}, {%0,%1,%2,%3};\n"
        : "+f"(c[0]), "+f"(c[1]), "+f"(c[2]), "+f"(c[3])
        : "r"(a[0]), "r"(a[1]), "r"(a[2]), "r"(a[3]), "r"(b[0]), "r"(b[1]));
}

// ---------------- 1) normalize cls_emb rows -> bf16 ----------------
__global__ void norm_kernel(const float* __restrict__ cls) {
    int warp = (blockIdx.x * blockDim.x + threadIdx.x) >> 5;
    int lane = threadIdx.x & 31;
    if (warp >= B_ROWS) return;
    const float* row = cls + (size_t)warp * DDIM;
    float s = 0.f;
#pragma unroll
    for (int k = lane; k < DDIM; k += 32) { float v = row[k]; s += v * v; }
#pragma unroll
    for (int off = 16; off > 0; off >>= 1) s += __shfl_xor_sync(0xffffffffu, s, off);
    float r = rsqrtf(s);
    __nv_bfloat16* dst = g_en + (size_t)warp * DDIM;
#pragma unroll
    for (int k = lane; k < DDIM; k += 32) dst[k] = __float2bfloat16(row[k] * r);
}

// ---------------- 2) label histogram (single block -> deterministic) ----------------
__global__ void hist_kernel(const int* __restrict__ labels) {
    __shared__ int h[NLAB];
    if (threadIdx.x < NLAB) h[threadIdx.x] = 0;
    __syncthreads();
    for (int i = threadIdx.x; i < B_ROWS; i += blockDim.x) atomicAdd(&h[labels[i]], 1);
    __syncthreads();
    if (threadIdx.x < NLAB) g_cnt[threadIdx.x] = h[threadIdx.x];
}

// ---------------- 3) logits + per-row CE ----------------
__global__ void logits_kernel(const float* __restrict__ pooled,
                              const float* __restrict__ W,
                              const float* __restrict__ bias,
                              const int* __restrict__ labels,
                              float* __restrict__ out_logits) {
    int i = blockIdx.x;
    __shared__ float sx[DDIM];
    __shared__ float sl[NLAB];
    const float* row = pooled + (size_t)i * DDIM;
    for (int k = threadIdx.x; k < DDIM; k += blockDim.x) sx[k] = row[k];
    __syncthreads();
    int w = threadIdx.x >> 5, lane = threadIdx.x & 31;
    if (w < NLAB) {
        const float* wr = W + (size_t)w * DDIM;
        float s = 0.f;
#pragma unroll
        for (int k = lane; k < DDIM; k += 32) s += sx[k] * wr[k];
#pragma unroll
        for (int off = 16; off > 0; off >>= 1) s += __shfl_xor_sync(0xffffffffu, s, off);
        if (lane == 0) { s += bias[w]; sl[w] = s; out_logits[(size_t)i * NLAB + w] = s; }
    }
    __syncthreads();
    if (threadIdx.x == 0) {
        float mx = sl[0];
#pragma unroll
        for (int c = 1; c < NLAB; c++) mx = fmaxf(mx, sl[c]);
        float se = 0.f;
#pragma unroll
        for (int c = 0; c < NLAB; c++) se += expf(sl[c] - mx);
        float lse = mx + logf(se);
        g_ce[i] = lse - sl[labels[i]];
    }
}

// ---------------- 4) fused S = en*en^T / T with streaming masked softmax stats ----------------
__global__ __launch_bounds__(256, 1)
void contrast_kernel(const int* __restrict__ labels) {
    __shared__ __align__(16) char buf[(BM * PAD_K + BN * PAD_K) * 2];  // 36864 B; staging 33280 B fits
    __shared__ int sLab[BN];
    __nv_bfloat16* sA = (__nv_bfloat16*)buf;
    __nv_bfloat16* sB = (__nv_bfloat16*)(buf + BM * PAD_K * 2);
    float* sS = (float*)buf;  // reused after K-loop

    const int tid = threadIdx.x;
    const int lane = tid & 31;
    const int wid = tid >> 5;
    const int wm = wid >> 1;     // 0..3 -> rows wm*32
    const int wn = wid & 1;      // 0..1 -> cols wn*64
    const int rowBase = (blockIdx.x >> 1) * BM;
    const int split = blockIdx.x & 1;

    const int myRow = rowBase + (tid >> 1);
    const int q = tid & 1;
    const int myLab = labels[myRow];

    float run_max = -INFINITY, run_sum = 0.f, run_pos = 0.f;
    const float invT = 1.0f / TEMP;

    const int ctBeg = split * (B_ROWS / BN / NSPLIT);
    const int ctEnd = ctBeg + (B_ROWS / BN / NSPLIT);

    for (int ct = ctBeg; ct < ctEnd; ct++) {
        const int colBase = ct * BN;
        __syncthreads();  // previous tile's reduction finished with sS / sLab
        if (tid < BN) sLab[tid] = labels[colBase + tid];

        float acc[2][8][4];
#pragma unroll
        for (int mf = 0; mf < 2; mf++)
#pragma unroll
            for (int nf = 0; nf < 8; nf++)
#pragma unroll
                for (int e = 0; e < 4; e++) acc[mf][nf][e] = 0.f;

        for (int kc = 0; kc < DDIM / BK; kc++) {
            __syncthreads();
#pragma unroll
            for (int it = 0; it < 4; it++) {   // A tile: 128x64 bf16 = 1024 uint4
                int idx = tid + 256 * it;
                int r = idx >> 3, c8 = idx & 7;
                uint4 v = *(const uint4*)(g_en + (size_t)(rowBase + r) * DDIM + kc * BK + c8 * 8);
                *(uint4*)(sA + r * PAD_K + c8 * 8) = v;
            }
#pragma unroll
            for (int it = 0; it < 4; it++) {   // B tile
                int idx = tid + 256 * it;
                int r = idx >> 3, c8 = idx & 7;
                uint4 v = *(const uint4*)(g_en + (size_t)(colBase + r) * DDIM + kc * BK + c8 * 8);
                *(uint4*)(sB + r * PAD_K + c8 * 8) = v;
            }
            __syncthreads();
#pragma unroll
            for (int ks = 0; ks < BK / 16; ks++) {
                uint32_t a[2][4];
#pragma unroll
                for (int mf = 0; mf < 2; mf++) {
                    int row = wm * 32 + mf * 16 + (lane & 15);
                    int kcol = ks * 16 + (lane >> 4) * 8;
                    ldsm_x4(a[mf], sA + row * PAD_K + kcol);
                }
                uint32_t bb[8][2];
#pragma unroll
                for (int nf2 = 0; nf2 < 4; nf2++) {
                    int mi = lane >> 3;
                    int rrow = wn * 64 + nf2 * 16 + ((mi >> 1) << 3) + (lane & 7);
                    int kk = ks * 16 + ((mi & 1) << 3);
                    ldsm_x4(&bb[nf2 * 2][0], sB + rrow * PAD_K + kk);
                }
#pragma unroll
                for (int mf = 0; mf < 2; mf++)
#pragma unroll
                    for (int nf = 0; nf < 8; nf++)
                        mma_bf16(acc[mf][nf], a[mf], bb[nf]);
            }
        }

        // two 64-column halves: stage to smem, then online reduce
#pragma unroll
        for (int h = 0; h < 2; h++) {
            __syncthreads();  // operands (h=0) / previous half's reads (h=1) done
            if (wn == h) {
#pragma unroll
                for (int mf = 0; mf < 2; mf++)
#pragma unroll
                    for (int nf = 0; nf < 8; nf++) {
                        int r0 = wm * 32 + mf * 16 + (lane >> 2);
                        int c0 = nf * 8 + (lane & 3) * 2;
                        sS[r0 * SS_LD + c0]            = acc[mf][nf][0] * invT;
                        sS[r0 * SS_LD + c0 + 1]        = acc[mf][nf][1] * invT;
                        sS[(r0 + 8) * SS_LD + c0]      = acc[mf][nf][2] * invT;
                        sS[(r0 + 8) * SS_LD + c0 + 1]  = acc[mf][nf][3] * invT;
                    }
            }
            __syncthreads();

            const int r = tid >> 1;
            const int cb = colBase + h * 64;
            float m = -INFINITY;
#pragma unroll 8
            for (int k = 0; k < 32; k++) {
                int c = q * 32 + k;
                float s = sS[r * SS_LD + c];
                if (cb + c != myRow) m = fmaxf(m, s);
            }
            m = fmaxf(m, __shfl_xor_sync(0xffffffffu, m, 1));
            float nm = fmaxf(run_max, m);
            float esum = 0.f, pp = 0.f;
#pragma unroll 8
            for (int k = 0; k < 32; k++) {
                int c = q * 32 + k;
                float s = sS[r * SS_LD + c];
                if (cb + c != myRow) {
                    esum += __expf(s - nm);
                    if (sLab[h * 64 + c] == myLab) pp += s;
                }
            }
            esum += __shfl_xor_sync(0xffffffffu, esum, 1);
            pp   += __shfl_xor_sync(0xffffffffu, pp, 1);
            run_sum = run_sum * __expf(run_max - nm) + esum;
            run_pos += pp;
            run_max = nm;
        }
    }

    if (q == 0) {
        g_m[split * B_ROWS + myRow] = run_max;
        g_s[split * B_ROWS + myRow] = run_sum;
        g_p[split * B_ROWS + myRow] = run_pos;
    }
}

// ---------------- 5) merge splits + final loss ----------------
__global__ void finalize_kernel(const int* __restrict__ labels, float* __restrict__ d_out) {
    __shared__ float sc[1024], se[1024];
    int t = threadIdx.x;
    float c = 0.f, e = 0.f;
    for (int i = t; i < B_ROWS; i += 1024) {
        float m0 = g_m[i],          m1 = g_m[B_ROWS + i];
        float s0 = g_s[i],          s1 = g_s[B_ROWS + i];
        float p  = g_p[i] + g_p[B_ROWS + i];
        float nm = fmaxf(m0, m1);
        float ss = s0 * __expf(m0 - nm) + s1 * __expf(m1 - nm);
        float lse = nm + logf(ss);
        int ni = g_cnt[labels[i]] - 1;
        float pa = (ni > 0) ? (lse - p / (float)ni) : 0.f;
        c += pa;
        e += g_ce[i];
    }
    sc[t] = c; se[t] = e;
    __syncthreads();
    for (int s = 512; s > 0; s >>= 1) {
        if (t < s) { sc[t] += sc[t + s]; se[t] += se[t + s]; }
        __syncthreads();
    }
    if (t == 0) d_out[0] = LAM * sc[0] + (1.0f - LAM) * (se[0] / (float)B_ROWS);
}

// ---------------- launch ----------------
extern "C" void kernel_launch(void* const* d_in, const int* in_sizes, int n_in,
                              void* d_out, int out_size) {
    const float* cls    = (const float*)d_in[0];
    const float* pooled = (const float*)d_in[1];
    const int*   labels = (const int*)d_in[2];
    const float* W      = (const float*)d_in[3];
    const float* bias   = (const float*)d_in[4];
    float* out = (float*)d_out;   // [0] = loss, [1..] = logits (8192 x 7)

    norm_kernel<<<B_ROWS / 8, 256>>>(cls);
    hist_kernel<<<1, 256>>>(labels);
    logits_kernel<<<B_ROWS, 256>>>(pooled, W, bias, labels, out + 1);
    contrast_kernel<<<(B_ROWS / BM) * NSPLIT, 256>>>(labels);
    finalize_kernel<<<1, 1024>>>(labels, out);
}

// round 2
// speedup vs baseline: 1.5911x; 1.5911x over previous
#include <cuda_runtime.h>
#include <cuda_bf16.h>
#include <cstdint>

#define B_ROWS 8192
#define DDIM   768
#define NLAB   7
#define TEMP   0.3f
#define LAM    0.9f
#define NT     64          // 128-row tile count
#define NTILES 2080        // NT*(NT+1)/2 upper-tri tiles

#define BM 128
#define BN 128
#define BK 32
#define PADK 40            // bf16 elems per smem row (80B stride, ldmatrix conflict-free)

// ---------------- static device scratch ----------------
__device__ __nv_bfloat16 g_en[B_ROWS * DDIM];
__device__ float g_part[NT][B_ROWS];     // exp-sum partials, one slot per tile-col per row
__device__ float g_pos[B_ROWS];
__device__ float g_ce[B_ROWS];
__device__ float g_Zpart[64][NLAB * DDIM];
__device__ float g_Z[NLAB * DDIM];
__device__ int   g_cnt[NLAB];

// ---------------- helpers ----------------
__device__ __forceinline__ void ldsm_x4(uint32_t* r, const void* p) {
    uint32_t addr = (uint32_t)__cvta_generic_to_shared(p);
    asm volatile("ldmatrix.sync.aligned.m8n8.x4.shared.b16 {%0,%1,%2,%3}, [%4];"
                 : "=r"(r[0]), "=r"(r[1]), "=r"(r[2]), "=r"(r[3]) : "r"(addr));
}

__device__ __forceinline__ void mma_bf16(float* c, const uint32_t* a, const uint32_t* b) {
    asm volatile(
        "mma.sync.aligned.m16n8k16.row.col.f32.bf16.bf16.f32 "
        "{%0,%1,%2,%3}, {%4,%5,%6,%7}, {%8,%9}, {%0,%1,%2,%3};\n"
        : "+f"(c[0]), "+f"(c[1]), "+f"(c[2]), "+f"(c[3])
        : "r"(a[0]), "r"(a[1]), "r"(a[2]), "r"(a[3]), "r"(b[0]), "r"(b[1]));
}

__device__ __forceinline__ void cp16(void* smem, const void* gmem) {
    uint32_t s = (uint32_t)__cvta_generic_to_shared(smem);
    asm volatile("cp.async.cg.shared.global [%0], [%1], 16;\n" :: "r"(s), "l"(gmem));
}
#define CP_COMMIT() asm volatile("cp.async.commit_group;\n" ::: "memory")

// ---------------- 1) normalize cls rows -> bf16 ----------------
__global__ void norm_kernel(const float* __restrict__ cls) {
    int warp = (blockIdx.x * blockDim.x + threadIdx.x) >> 5;
    int lane = threadIdx.x & 31;
    if (warp >= B_ROWS) return;
    const float* row = cls + (size_t)warp * DDIM;
    float s = 0.f;
#pragma unroll
    for (int k = lane; k < DDIM; k += 32) { float v = row[k]; s += v * v; }
#pragma unroll
    for (int off = 16; off > 0; off >>= 1) s += __shfl_xor_sync(0xffffffffu, s, off);
    float r = rsqrtf(s);
    __nv_bfloat16* dst = g_en + (size_t)warp * DDIM;
#pragma unroll
    for (int k = lane; k < DDIM; k += 32) dst[k] = __float2bfloat16(row[k] * r);
}

// ---------------- 2) label histogram ----------------
__global__ void hist_kernel(const int* __restrict__ labels) {
    __shared__ int h[NLAB];
    if (threadIdx.x < NLAB) h[threadIdx.x] = 0;
    __syncthreads();
    for (int i = threadIdx.x; i < B_ROWS; i += blockDim.x) atomicAdd(&h[labels[i]], 1);
    __syncthreads();
    if (threadIdx.x < NLAB) g_cnt[threadIdx.x] = h[threadIdx.x];
}

// ---------------- 3) logits + per-row CE ----------------
__global__ void logits_kernel(const float* __restrict__ pooled,
                              const float* __restrict__ W,
                              const float* __restrict__ bias,
                              const int* __restrict__ labels,
                              float* __restrict__ out_logits) {
    int i = blockIdx.x;
    __shared__ float sx[DDIM];
    __shared__ float sl[NLAB];
    const float* row = pooled + (size_t)i * DDIM;
    for (int k = threadIdx.x; k < DDIM; k += blockDim.x) sx[k] = row[k];
    __syncthreads();
    int w = threadIdx.x >> 5, lane = threadIdx.x & 31;
    if (w < NLAB) {
        const float* wr = W + (size_t)w * DDIM;
        float s = 0.f;
#pragma unroll
        for (int k = lane; k < DDIM; k += 32) s += sx[k] * wr[k];
#pragma unroll
        for (int off = 16; off > 0; off >>= 1) s += __shfl_xor_sync(0xffffffffu, s, off);
        if (lane == 0) { s += bias[w]; sl[w] = s; out_logits[(size_t)i * NLAB + w] = s; }
    }
    __syncthreads();
    if (threadIdx.x == 0) {
        float mx = sl[0];
#pragma unroll
        for (int c = 1; c < NLAB; c++) mx = fmaxf(mx, sl[c]);
        float se = 0.f;
#pragma unroll
        for (int c = 0; c < NLAB; c++) se += expf(sl[c] - mx);
        g_ce[i] = mx + logf(se) - sl[labels[i]];
    }
}

// ---------------- 4) per-label embedding sums Z (partial, deterministic) ----------------
__global__ void zsum_kernel(const int* __restrict__ labels) {
    __shared__ float sZ[NLAB * DDIM];
    for (int i = threadIdx.x; i < NLAB * DDIM; i += 256) sZ[i] = 0.f;
    __syncthreads();
    int r0 = blockIdx.x * 128;
    for (int rr = 0; rr < 128; rr++) {
        int r = r0 + rr;
        int l = labels[r];
        const __nv_bfloat16* row = g_en + (size_t)r * DDIM;
        for (int k = threadIdx.x; k < DDIM; k += 256)
            sZ[l * DDIM + k] += __bfloat162float(row[k]);
    }
    __syncthreads();
    for (int i = threadIdx.x; i < NLAB * DDIM; i += 256) g_Zpart[blockIdx.x][i] = sZ[i];
}

__global__ void zred_kernel() {
    int i = blockIdx.x * 256 + threadIdx.x;
    if (i < NLAB * DDIM) {
        float s = 0.f;
#pragma unroll 8
        for (int b = 0; b < 64; b++) s += g_Zpart[b][i];
        g_Z[i] = s;
    }
}

// ---------------- 5) pos_r = (en_r . Z[lab_r] - ||en_r||^2) / T ----------------
__global__ void pos_kernel(const int* __restrict__ labels) {
    int row = blockIdx.x * 8 + (threadIdx.x >> 5);
    int lane = threadIdx.x & 31;
    int l = labels[row];
    const __nv_bfloat16* e = g_en + (size_t)row * DDIM;
    const float* z = g_Z + l * DDIM;
    float dot = 0.f, d = 0.f;
#pragma unroll
    for (int k = lane; k < DDIM; k += 32) {
        float v = __bfloat162float(e[k]);
        dot += v * z[k];
        d += v * v;
    }
#pragma unroll
    for (int off = 16; off > 0; off >>= 1) {
        dot += __shfl_xor_sync(0xffffffffu, dot, off);
        d   += __shfl_xor_sync(0xffffffffu, d, off);
    }
    if (lane == 0) g_pos[row] = (dot - d) * (1.0f / TEMP);
}

// ---------------- 6) upper-tri tiles: S tile GEMM + exp row/col partial sums ----------------
__global__ __launch_bounds__(256, 2)
void contrast_kernel() {
    __shared__ __align__(16) __nv_bfloat16 sbuf[2][256 * PADK];  // 40960 B

    const int tid = threadIdx.x;
    const int lane = tid & 31;
    const int wid = tid >> 5;
    const int wm = wid >> 1;  // 0..3 (rows wm*32)
    const int wn = wid & 1;   // 0..1 (cols wn*64)

    // tile index -> (I, J), I <= J
    int t = blockIdx.x;
    int I = (int)(64.5f - sqrtf(64.5f * 64.5f - 2.0f * (float)t));
    while ((I + 1) * NT - ((I + 1) * I) / 2 <= t) ++I;
    while (I * NT - (I * (I - 1)) / 2 > t) --I;
    const int J = I + (t - (I * NT - (I * (I - 1)) / 2));
    const int rowBase = I * BM;
    const int colBase = J * BN;

    float acc[2][8][4];
#pragma unroll
    for (int mf = 0; mf < 2; mf++)
#pragma unroll
        for (int nf = 0; nf < 8; nf++)
#pragma unroll
            for (int e = 0; e < 4; e++) acc[mf][nf][e] = 0.f;

    // ---- prologue: stage 0 ----
    {
        const __nv_bfloat16* base = g_en;  // kc = 0
#pragma unroll
        for (int it = 0; it < 4; it++) {
            int idx = tid + 256 * it;
            int r = idx >> 2;
            int c8 = (idx & 3) * 8;
            int gr = (r < BM) ? (rowBase + r) : (colBase + r - BM);
            cp16(&sbuf[0][r * PADK + c8], base + (size_t)gr * DDIM + c8);
        }
        CP_COMMIT();
    }

    // ---- mainloop: 24 k-chunks, 2-stage cp.async pipeline ----
#pragma unroll 1
    for (int kc = 0; kc < DDIM / BK; kc++) {
        if (kc + 1 < DDIM / BK) {
            const __nv_bfloat16* base = g_en + (kc + 1) * BK;
            __nv_bfloat16* dbuf = sbuf[(kc + 1) & 1];
#pragma unroll
            for (int it = 0; it < 4; it++) {
                int idx = tid + 256 * it;
                int r = idx >> 2;
                int c8 = (idx & 3) * 8;
                int gr = (r < BM) ? (rowBase + r) : (colBase + r - BM);
                cp16(&dbuf[r * PADK + c8], base + (size_t)gr * DDIM + c8);
            }
            CP_COMMIT();
            asm volatile("cp.async.wait_group 1;\n" ::: "memory");
        } else {
            asm volatile("cp.async.wait_group 0;\n" ::: "memory");
        }
        __syncthreads();

        const __nv_bfloat16* sA = sbuf[kc & 1];
        const __nv_bfloat16* sB = sA + 128 * PADK;
#pragma unroll
        for (int ks = 0; ks < BK / 16; ks++) {
            uint32_t a[2][4];
#pragma unroll
            for (int mf = 0; mf < 2; mf++) {
                int row = wm * 32 + mf * 16 + (lane & 15);
                int kcol = ks * 16 + (lane >> 4) * 8;
                ldsm_x4(a[mf], sA + row * PADK + kcol);
            }
            uint32_t bb[8][2];
#pragma unroll
            for (int nf2 = 0; nf2 < 4; nf2++) {
                int mi = lane >> 3;
                int rrow = wn * 64 + nf2 * 16 + ((mi >> 1) << 3) + (lane & 7);
                int kk = ks * 16 + ((mi & 1) << 3);
                ldsm_x4(&bb[nf2 * 2][0], sB + rrow * PADK + kk);
            }
#pragma unroll
            for (int mf = 0; mf < 2; mf++)
#pragma unroll
                for (int nf = 0; nf < 8; nf++)
                    mma_bf16(acc[mf][nf], a[mf], bb[nf]);
        }
        __syncthreads();
    }

    // ---- epilogue: exp (no max needed: s/T in [-3.34, 3.34]) + row/col partials ----
    const float invT = 1.0f / TEMP;
    float rs[4] = {0.f, 0.f, 0.f, 0.f};
    float cs[16];
#pragma unroll
    for (int j = 0; j < 16; j++) cs[j] = 0.f;

    if (I != J) {
#pragma unroll
        for (int mf = 0; mf < 2; mf++)
#pragma unroll
            for (int nf = 0; nf < 8; nf++) {
                float e0 = __expf(acc[mf][nf][0] * invT);
                float e1 = __expf(acc[mf][nf][1] * invT);
                float e2 = __expf(acc[mf][nf][2] * invT);
                float e3 = __expf(acc[mf][nf][3] * invT);
                rs[mf * 2 + 0] += e0 + e1;
                rs[mf * 2 + 1] += e2 + e3;
                cs[nf * 2 + 0] += e0 + e2;
                cs[nf * 2 + 1] += e1 + e3;
            }
    } else {
        const int r0 = wm * 32 + (lane >> 2);
        const int c0 = wn * 64 + (lane & 3) * 2;
#pragma unroll
        for (int mf = 0; mf < 2; mf++)
#pragma unroll
            for (int nf = 0; nf < 8; nf++) {
                int rr = r0 + mf * 16, cc = c0 + nf * 8;
                float e0 = (cc     > rr    ) ? __expf(acc[mf][nf][0] * invT) : 0.f;
                float e1 = (cc + 1 > rr    ) ? __expf(acc[mf][nf][1] * invT) : 0.f;
                float e2 = (cc     > rr + 8) ? __expf(acc[mf][nf][2] * invT) : 0.f;
                float e3 = (cc + 1 > rr + 8) ? __expf(acc[mf][nf][3] * invT) : 0.f;
                rs[mf * 2 + 0] += e0 + e1;
                rs[mf * 2 + 1] += e2 + e3;
                cs[nf * 2 + 0] += e0 + e2;
                cs[nf * 2 + 1] += e1 + e3;
            }
    }

    // reduce rows across lanes sharing the same row (lane&3)
#pragma unroll
    for (int j = 0; j < 4; j++) {
        rs[j] += __shfl_xor_sync(0xffffffffu, rs[j], 1);
        rs[j] += __shfl_xor_sync(0xffffffffu, rs[j], 2);
    }
    // reduce cols across lanes sharing the same col (lane>>2)
#pragma unroll
    for (int j = 0; j < 16; j++) {
        cs[j] += __shfl_xor_sync(0xffffffffu, cs[j], 4);
        cs[j] += __shfl_xor_sync(0xffffffffu, cs[j], 8);
        cs[j] += __shfl_xor_sync(0xffffffffu, cs[j], 16);
    }

    float* srow = (float*)sbuf;        // [2][128]
    float* scol = srow + 2 * 128;      // [4][128]
    if ((lane & 3) == 0) {
#pragma unroll
        for (int j = 0; j < 4; j++) {
            int row = wm * 32 + (j >> 1) * 16 + (lane >> 2) + (j & 1) * 8;
            srow[wn * 128 + row] = rs[j];
        }
    }
    if (lane < 4) {
#pragma unroll
        for (int j = 0; j < 16; j++) {
            int col = wn * 64 + (j >> 1) * 8 + lane * 2 + (j & 1);
            scol[wm * 128 + col] = cs[j];
        }
    }
    __syncthreads();

    if (tid < 128) {
        float rsum = srow[tid] + srow[128 + tid];
        float csum = scol[tid] + scol[128 + tid] + scol[256 + tid] + scol[384 + tid];
        if (I == J) {
            g_part[I][rowBase + tid] = rsum + csum;
        } else {
            g_part[J][rowBase + tid] = rsum;   // rows of block I, slot J
            g_part[I][colBase + tid] = csum;   // rows of block J, slot I
        }
    }
}

// ---------------- 7) final loss ----------------
__global__ void finalize_kernel(const int* __restrict__ labels, float* __restrict__ d_out) {
    __shared__ float sc[256], se[256];
    int t = threadIdx.x;
    float c = 0.f, e = 0.f;
    for (int r = t; r < B_ROWS; r += 256) {
        float es = 0.f;
#pragma unroll 8
        for (int j = 0; j < NT; j++) es += g_part[j][r];
        float lse = logf(es);
        int ni = g_cnt[labels[r]] - 1;
        float pa = (ni > 0) ? (lse - g_pos[r] / (float)ni) : 0.f;
        c += pa;
        e += g_ce[r];
    }
    sc[t] = c; se[t] = e;
    __syncthreads();
    for (int s = 128; s > 0; s >>= 1) {
        if (t < s) { sc[t] += sc[t + s]; se[t] += se[t + s]; }
        __syncthreads();
    }
    if (t == 0) d_out[0] = LAM * sc[0] + (1.0f - LAM) * (se[0] / (float)B_ROWS);
}

// ---------------- launch ----------------
extern "C" void kernel_launch(void* const* d_in, const int* in_sizes, int n_in,
                              void* d_out, int out_size) {
    const float* cls    = (const float*)d_in[0];
    const float* pooled = (const float*)d_in[1];
    const int*   labels = (const int*)d_in[2];
    const float* W      = (const float*)d_in[3];
    const float* bias   = (const float*)d_in[4];
    float* out = (float*)d_out;   // [0] = loss, [1..] = logits

    norm_kernel<<<B_ROWS / 8, 256>>>(cls);
    hist_kernel<<<1, 256>>>(labels);
    logits_kernel<<<B_ROWS, 256>>>(pooled, W, bias, labels, out + 1);
    zsum_kernel<<<64, 256>>>(labels);
    zred_kernel<<<(NLAB * DDIM + 255) / 256, 256>>>();
    pos_kernel<<<B_ROWS / 8, 256>>>(labels);
    contrast_kernel<<<NTILES, 256>>>();
    finalize_kernel<<<1, 256>>>(labels, out);
}

// round 3
// speedup vs baseline: 1.9395x; 1.2190x over previous
#include <cuda_runtime.h>
#include <cuda_bf16.h>
#include <cstdint>

#define B_ROWS 8192
#define DDIM   768
#define NLAB   7
#define TEMP   0.3f
#define LAM    0.9f
#define NT     64          // 128-row tile count
#define NTILES 2080        // NT*(NT+1)/2 upper-tri tiles

#define BM 128
#define BN 128
#define BK 32
#define PADK 40            // bf16 elems per smem row (80B stride, ldmatrix conflict-free)
#define NSTAGE 3

#define ZBLK 128
#define ZROWS (B_ROWS / ZBLK)   // 64

// ---------------- static device scratch ----------------
__device__ __nv_bfloat16 g_en[B_ROWS * DDIM];
__device__ float g_part[NT][B_ROWS];     // exp-sum partials, one slot per tile-col per row
__device__ float g_pos[B_ROWS];
__device__ float g_ce[B_ROWS];
__device__ float g_Zpart[ZBLK][NLAB * DDIM];
__device__ float g_Z[NLAB * DDIM];
__device__ int   g_cnt[NLAB];

// ---------------- helpers ----------------
__device__ __forceinline__ void ldsm_x4(uint32_t* r, const void* p) {
    uint32_t addr = (uint32_t)__cvta_generic_to_shared(p);
    asm volatile("ldmatrix.sync.aligned.m8n8.x4.shared.b16 {%0,%1,%2,%3}, [%4];"
                 : "=r"(r[0]), "=r"(r[1]), "=r"(r[2]), "=r"(r[3]) : "r"(addr));
}

__device__ __forceinline__ void mma_bf16(float* c, const uint32_t* a, const uint32_t* b) {
    asm volatile(
        "mma.sync.aligned.m16n8k16.row.col.f32.bf16.bf16.f32 "
        "{%0,%1,%2,%3}, {%4,%5,%6,%7}, {%8,%9}, {%0,%1,%2,%3};\n"
        : "+f"(c[0]), "+f"(c[1]), "+f"(c[2]), "+f"(c[3])
        : "r"(a[0]), "r"(a[1]), "r"(a[2]), "r"(a[3]), "r"(b[0]), "r"(b[1]));
}

__device__ __forceinline__ void cp16(void* smem, const void* gmem) {
    uint32_t s = (uint32_t)__cvta_generic_to_shared(smem);
    asm volatile("cp.async.cg.shared.global [%0], [%1], 16;\n" :: "r"(s), "l"(gmem));
}
#define CP_COMMIT() asm volatile("cp.async.commit_group;\n" ::: "memory")

// ---------------- 1) normalize cls rows -> bf16 ----------------
__global__ void norm_kernel(const float* __restrict__ cls) {
    int warp = (blockIdx.x * blockDim.x + threadIdx.x) >> 5;
    int lane = threadIdx.x & 31;
    if (warp >= B_ROWS) return;
    const float* row = cls + (size_t)warp * DDIM;
    float s = 0.f;
#pragma unroll
    for (int k = lane; k < DDIM; k += 32) { float v = row[k]; s += v * v; }
#pragma unroll
    for (int off = 16; off > 0; off >>= 1) s += __shfl_xor_sync(0xffffffffu, s, off);
    float r = rsqrtf(s);
    __nv_bfloat16* dst = g_en + (size_t)warp * DDIM;
#pragma unroll
    for (int k = lane; k < DDIM; k += 32) dst[k] = __float2bfloat16(row[k] * r);
}

// ---------------- 2) label histogram ----------------
__global__ void hist_kernel(const int* __restrict__ labels) {
    __shared__ int h[NLAB];
    if (threadIdx.x < NLAB) h[threadIdx.x] = 0;
    __syncthreads();
    for (int i = threadIdx.x; i < B_ROWS; i += blockDim.x) atomicAdd(&h[labels[i]], 1);
    __syncthreads();
    if (threadIdx.x < NLAB) g_cnt[threadIdx.x] = h[threadIdx.x];
}

// ---------------- 3) logits + per-row CE ----------------
__global__ void logits_kernel(const float* __restrict__ pooled,
                              const float* __restrict__ W,
                              const float* __restrict__ bias,
                              const int* __restrict__ labels,
                              float* __restrict__ out_logits) {
    int i = blockIdx.x;
    __shared__ float sx[DDIM];
    __shared__ float sl[NLAB];
    const float* row = pooled + (size_t)i * DDIM;
    for (int k = threadIdx.x; k < DDIM; k += blockDim.x) sx[k] = row[k];
    __syncthreads();
    int w = threadIdx.x >> 5, lane = threadIdx.x & 31;
    if (w < NLAB) {
        const float* wr = W + (size_t)w * DDIM;
        float s = 0.f;
#pragma unroll
        for (int k = lane; k < DDIM; k += 32) s += sx[k] * wr[k];
#pragma unroll
        for (int off = 16; off > 0; off >>= 1) s += __shfl_xor_sync(0xffffffffu, s, off);
        if (lane == 0) { s += bias[w]; sl[w] = s; out_logits[(size_t)i * NLAB + w] = s; }
    }
    __syncthreads();
    if (threadIdx.x == 0) {
        float mx = sl[0];
#pragma unroll
        for (int c = 1; c < NLAB; c++) mx = fmaxf(mx, sl[c]);
        float se = 0.f;
#pragma unroll
        for (int c = 0; c < NLAB; c++) se += expf(sl[c] - mx);
        g_ce[i] = mx + logf(se) - sl[labels[i]];
    }
}

// ---------------- 4) per-label embedding sums Z (register-resident partials) ----------------
__global__ __launch_bounds__(256)
void zsum_kernel(const int* __restrict__ labels) {
    __shared__ int sLab[ZROWS];
    const int t = threadIdx.x;
    if (t < ZROWS) sLab[t] = labels[blockIdx.x * ZROWS + t];
    __syncthreads();

    float acc[NLAB][3];
#pragma unroll
    for (int l = 0; l < NLAB; l++)
#pragma unroll
        for (int c = 0; c < 3; c++) acc[l][c] = 0.f;

    const int r0 = blockIdx.x * ZROWS;
#pragma unroll 4
    for (int rr = 0; rr < ZROWS; rr++) {
        const int lab = sLab[rr];
        const __nv_bfloat16* row = g_en + (size_t)(r0 + rr) * DDIM;
#pragma unroll
        for (int c = 0; c < 3; c++) {
            float v = __bfloat162float(row[t + c * 256]);
#pragma unroll
            for (int l = 0; l < NLAB; l++)
                acc[l][c] += (l == lab) ? v : 0.f;
        }
    }
#pragma unroll
    for (int l = 0; l < NLAB; l++)
#pragma unroll
        for (int c = 0; c < 3; c++)
            g_Zpart[blockIdx.x][l * DDIM + t + c * 256] = acc[l][c];
}

__global__ void zred_kernel() {
    int i = blockIdx.x * 256 + threadIdx.x;
    if (i < NLAB * DDIM) {
        float s = 0.f;
#pragma unroll 8
        for (int b = 0; b < ZBLK; b++) s += g_Zpart[b][i];
        g_Z[i] = s;
    }
}

// ---------------- 5) pos_r = (en_r . Z[lab_r] - ||en_r||^2) / T ----------------
__global__ void pos_kernel(const int* __restrict__ labels) {
    int row = blockIdx.x * 8 + (threadIdx.x >> 5);
    int lane = threadIdx.x & 31;
    int l = labels[row];
    const __nv_bfloat16* e = g_en + (size_t)row * DDIM;
    const float* z = g_Z + l * DDIM;
    float dot = 0.f, d = 0.f;
#pragma unroll
    for (int k = lane; k < DDIM; k += 32) {
        float v = __bfloat162float(e[k]);
        dot += v * z[k];
        d += v * v;
    }
#pragma unroll
    for (int off = 16; off > 0; off >>= 1) {
        dot += __shfl_xor_sync(0xffffffffu, dot, off);
        d   += __shfl_xor_sync(0xffffffffu, d, off);
    }
    if (lane == 0) g_pos[row] = (dot - d) * (1.0f / TEMP);
}

// ---------------- 6) upper-tri tiles: S tile GEMM + exp row/col partial sums ----------------
__global__ __launch_bounds__(256, 2)
void contrast_kernel() {
    __shared__ __align__(16) __nv_bfloat16 sbuf[NSTAGE][256 * PADK];  // 61440 B

    const int tid = threadIdx.x;
    const int lane = tid & 31;
    const int wid = tid >> 5;
    const int wm = wid >> 1;  // 0..3 (rows wm*32)
    const int wn = wid & 1;   // 0..1 (cols wn*64)

    // tile index -> (I, J), I <= J
    int t = blockIdx.x;
    int I = (int)(64.5f - sqrtf(64.5f * 64.5f - 2.0f * (float)t));
    while ((I + 1) * NT - ((I + 1) * I) / 2 <= t) ++I;
    while (I * NT - (I * (I - 1)) / 2 > t) --I;
    const int J = I + (t - (I * NT - (I * (I - 1)) / 2));
    const int rowBase = I * BM;
    const int colBase = J * BN;

    float acc[2][8][4];
#pragma unroll
    for (int mf = 0; mf < 2; mf++)
#pragma unroll
        for (int nf = 0; nf < 8; nf++)
#pragma unroll
            for (int e = 0; e < 4; e++) acc[mf][nf][e] = 0.f;

    const int NKC = DDIM / BK;  // 24

    // ---- prologue: issue stages 0,1 ----
#pragma unroll
    for (int p = 0; p < 2; p++) {
        const __nv_bfloat16* base = g_en + p * BK;
#pragma unroll
        for (int it = 0; it < 4; it++) {
            int idx = tid + 256 * it;
            int r = idx >> 2;
            int c8 = (idx & 3) * 8;
            int gr = (r < BM) ? (rowBase + r) : (colBase + r - BM);
            cp16(&sbuf[p][r * PADK + c8], base + (size_t)gr * DDIM + c8);
        }
        CP_COMMIT();
    }

    // ---- mainloop: 24 k-chunks, 3-stage cp.async pipeline ----
#pragma unroll 1
    for (int kc = 0; kc < NKC; kc++) {
        if (kc + 2 < NKC) {
            const __nv_bfloat16* base = g_en + (kc + 2) * BK;
            __nv_bfloat16* dbuf = sbuf[(kc + 2) % NSTAGE];
#pragma unroll
            for (int it = 0; it < 4; it++) {
                int idx = tid + 256 * it;
                int r = idx >> 2;
                int c8 = (idx & 3) * 8;
                int gr = (r < BM) ? (rowBase + r) : (colBase + r - BM);
                cp16(&dbuf[r * PADK + c8], base + (size_t)gr * DDIM + c8);
            }
            CP_COMMIT();
            asm volatile("cp.async.wait_group 2;\n" ::: "memory");
        } else if (kc + 2 == NKC) {
            asm volatile("cp.async.wait_group 1;\n" ::: "memory");
        } else {
            asm volatile("cp.async.wait_group 0;\n" ::: "memory");
        }
        __syncthreads();

        const __nv_bfloat16* sA = sbuf[kc % NSTAGE];
        const __nv_bfloat16* sB = sA + 128 * PADK;
#pragma unroll
        for (int ks = 0; ks < BK / 16; ks++) {
            uint32_t a[2][4];
#pragma unroll
            for (int mf = 0; mf < 2; mf++) {
                int row = wm * 32 + mf * 16 + (lane & 15);
                int kcol = ks * 16 + (lane >> 4) * 8;
                ldsm_x4(a[mf], sA + row * PADK + kcol);
            }
            uint32_t bb[8][2];
#pragma unroll
            for (int nf2 = 0; nf2 < 4; nf2++) {
                int mi = lane >> 3;
                int rrow = wn * 64 + nf2 * 16 + ((mi >> 1) << 3) + (lane & 7);
                int kk = ks * 16 + ((mi & 1) << 3);
                ldsm_x4(&bb[nf2 * 2][0], sB + rrow * PADK + kk);
            }
#pragma unroll
            for (int mf = 0; mf < 2; mf++)
#pragma unroll
                for (int nf = 0; nf < 8; nf++)
                    mma_bf16(acc[mf][nf], a[mf], bb[nf]);
        }
        __syncthreads();
    }

    // ---- epilogue: exp (no max needed: s/T in [-3.34, 3.34]) + row/col partials ----
    const float invT = 1.0f / TEMP;
    float rs[4] = {0.f, 0.f, 0.f, 0.f};
    float cs[16];
#pragma unroll
    for (int j = 0; j < 16; j++) cs[j] = 0.f;

    if (I != J) {
#pragma unroll
        for (int mf = 0; mf < 2; mf++)
#pragma unroll
            for (int nf = 0; nf < 8; nf++) {
                float e0 = __expf(acc[mf][nf][0] * invT);
                float e1 = __expf(acc[mf][nf][1] * invT);
                float e2 = __expf(acc[mf][nf][2] * invT);
                float e3 = __expf(acc[mf][nf][3] * invT);
                rs[mf * 2 + 0] += e0 + e1;
                rs[mf * 2 + 1] += e2 + e3;
                cs[nf * 2 + 0] += e0 + e2;
                cs[nf * 2 + 1] += e1 + e3;
            }
    } else {
        const int r0 = wm * 32 + (lane >> 2);
        const int c0 = wn * 64 + (lane & 3) * 2;
#pragma unroll
        for (int mf = 0; mf < 2; mf++)
#pragma unroll
            for (int nf = 0; nf < 8; nf++) {
                int rr = r0 + mf * 16, cc = c0 + nf * 8;
                float e0 = (cc     > rr    ) ? __expf(acc[mf][nf][0] * invT) : 0.f;
                float e1 = (cc + 1 > rr    ) ? __expf(acc[mf][nf][1] * invT) : 0.f;
                float e2 = (cc     > rr + 8) ? __expf(acc[mf][nf][2] * invT) : 0.f;
                float e3 = (cc + 1 > rr + 8) ? __expf(acc[mf][nf][3] * invT) : 0.f;
                rs[mf * 2 + 0] += e0 + e1;
                rs[mf * 2 + 1] += e2 + e3;
                cs[nf * 2 + 0] += e0 + e2;
                cs[nf * 2 + 1] += e1 + e3;
            }
    }

    // reduce rows across lanes sharing the same row (lane&3)
#pragma unroll
    for (int j = 0; j < 4; j++) {
        rs[j] += __shfl_xor_sync(0xffffffffu, rs[j], 1);
        rs[j] += __shfl_xor_sync(0xffffffffu, rs[j], 2);
    }
    // reduce cols across lanes sharing the same col (lane>>2)
#pragma unroll
    for (int j = 0; j < 16; j++) {
        cs[j] += __shfl_xor_sync(0xffffffffu, cs[j], 4);
        cs[j] += __shfl_xor_sync(0xffffffffu, cs[j], 8);
        cs[j] += __shfl_xor_sync(0xffffffffu, cs[j], 16);
    }

    float* srow = (float*)sbuf;        // [2][128]
    float* scol = srow + 2 * 128;      // [4][128]
    if ((lane & 3) == 0) {
#pragma unroll
        for (int j = 0; j < 4; j++) {
            int row = wm * 32 + (j >> 1) * 16 + (lane >> 2) + (j & 1) * 8;
            srow[wn * 128 + row] = rs[j];
        }
    }
    if (lane < 4) {
#pragma unroll
        for (int j = 0; j < 16; j++) {
            int col = wn * 64 + (j >> 1) * 8 + lane * 2 + (j & 1);
            scol[wm * 128 + col] = cs[j];
        }
    }
    __syncthreads();

    if (tid < 128) {
        float rsum = srow[tid] + srow[128 + tid];
        float csum = scol[tid] + scol[128 + tid] + scol[256 + tid] + scol[384 + tid];
        if (I == J) {
            g_part[I][rowBase + tid] = rsum + csum;
        } else {
            g_part[J][rowBase + tid] = rsum;   // rows of block I, slot J
            g_part[I][colBase + tid] = csum;   // rows of block J, slot I
        }
    }
}

// ---------------- 7) final loss ----------------
__global__ void finalize_kernel(const int* __restrict__ labels, float* __restrict__ d_out) {
    __shared__ float sc[256], se[256];
    int t = threadIdx.x;
    float c = 0.f, e = 0.f;
    for (int r = t; r < B_ROWS; r += 256) {
        float es = 0.f;
#pragma unroll 8
        for (int j = 0; j < NT; j++) es += g_part[j][r];
        float lse = logf(es);
        int ni = g_cnt[labels[r]] - 1;
        float pa = (ni > 0) ? (lse - g_pos[r] / (float)ni) : 0.f;
        c += pa;
        e += g_ce[r];
    }
    sc[t] = c; se[t] = e;
    __syncthreads();
    for (int s = 128; s > 0; s >>= 1) {
        if (t < s) { sc[t] += sc[t + s]; se[t] += se[t + s]; }
        __syncthreads();
    }
    if (t == 0) d_out[0] = LAM * sc[0] + (1.0f - LAM) * (se[0] / (float)B_ROWS);
}

// ---------------- launch ----------------
extern "C" void kernel_launch(void* const* d_in, const int* in_sizes, int n_in,
                              void* d_out, int out_size) {
    const float* cls    = (const float*)d_in[0];
    const float* pooled = (const float*)d_in[1];
    const int*   labels = (const int*)d_in[2];
    const float* W      = (const float*)d_in[3];
    const float* bias   = (const float*)d_in[4];
    float* out = (float*)d_out;   // [0] = loss, [1..] = logits

    norm_kernel<<<B_ROWS / 8, 256>>>(cls);
    hist_kernel<<<1, 256>>>(labels);
    logits_kernel<<<B_ROWS, 256>>>(pooled, W, bias, labels, out + 1);
    zsum_kernel<<<ZBLK, 256>>>(labels);
    zred_kernel<<<(NLAB * DDIM + 255) / 256, 256>>>();
    pos_kernel<<<B_ROWS / 8, 256>>>(labels);
    contrast_kernel<<<NTILES, 256>>>();
    finalize_kernel<<<1, 256>>>(labels, out);
}

// round 5
// speedup vs baseline: 2.1138x; 1.0898x over previous
#include <cuda_runtime.h>
#include <cuda_bf16.h>
#include <cuda_fp8.h>
#include <cstdint>

#define B_ROWS 8192
#define DDIM   768
#define NLAB   7
#define TEMP   0.3f
#define LAM    0.9f
#define NT     64          // 128-row tile count
#define NTILES 2080        // NT*(NT+1)/2 upper-tri tiles

#define BM 128
#define BN 128
#define BKB 64             // K-chunk bytes (64 fp8 elems)
#define PADB 80            // bytes per smem row (conflict-free ldmatrix)
#define NSTAGE 3
#define NKC (DDIM / BKB)   // 12

#define FP8_SCALE 16.0f

#define ZBLK 128
#define ZROWS (B_ROWS / ZBLK)   // 64

// ---------------- static device scratch ----------------
__device__ __nv_bfloat16 g_en[B_ROWS * DDIM];     // bf16 copy (zsum/pos)
__device__ uint8_t g_en8[B_ROWS * DDIM];          // e4m3, scaled x16 (contrast)
__device__ float g_part[NT][B_ROWS];
__device__ float g_pos[B_ROWS];
__device__ float g_ce[B_ROWS];
__device__ float g_Zpart[ZBLK][NLAB * DDIM];
__device__ float g_Z[NLAB * DDIM];
__device__ int   g_cnt[NLAB];

// ---------------- helpers ----------------
__device__ __forceinline__ void ldsm_x4(uint32_t* r, const void* p) {
    uint32_t addr = (uint32_t)__cvta_generic_to_shared(p);
    asm volatile("ldmatrix.sync.aligned.m8n8.x4.shared.b16 {%0,%1,%2,%3}, [%4];"
                 : "=r"(r[0]), "=r"(r[1]), "=r"(r[2]), "=r"(r[3]) : "r"(addr));
}

__device__ __forceinline__ void mma_fp8(float* c, const uint32_t* a, const uint32_t* b) {
    asm volatile(
        "mma.sync.aligned.m16n8k32.row.col.f32.e4m3.e4m3.f32 "
        "{%0,%1,%2,%3}, {%4,%5,%6,%7}, {%8,%9}, {%0,%1,%2,%3};\n"
        : "+f"(c[0]), "+f"(c[1]), "+f"(c[2]), "+f"(c[3])
        : "r"(a[0]), "r"(a[1]), "r"(a[2]), "r"(a[3]), "r"(b[0]), "r"(b[1]));
}

__device__ __forceinline__ void cp16(void* smem, const void* gmem) {
    uint32_t s = (uint32_t)__cvta_generic_to_shared(smem);
    asm volatile("cp.async.cg.shared.global [%0], [%1], 16;\n" :: "r"(s), "l"(gmem));
}
#define CP_COMMIT() asm volatile("cp.async.commit_group;\n" ::: "memory")

// ---------------- 1) normalize cls rows -> bf16 + scaled fp8 ----------------
__global__ void norm_kernel(const float* __restrict__ cls) {
    int warp = (blockIdx.x * blockDim.x + threadIdx.x) >> 5;
    int lane = threadIdx.x & 31;
    if (warp >= B_ROWS) return;
    const float* row = cls + (size_t)warp * DDIM;
    float s = 0.f;
#pragma unroll
    for (int k = lane; k < DDIM; k += 32) { float v = row[k]; s += v * v; }
#pragma unroll
    for (int off = 16; off > 0; off >>= 1) s += __shfl_xor_sync(0xffffffffu, s, off);
    float r = rsqrtf(s);
    __nv_bfloat16* dst = g_en + (size_t)warp * DDIM;
    uint8_t* dst8 = g_en8 + (size_t)warp * DDIM;
#pragma unroll
    for (int k = lane; k < DDIM; k += 32) {
        float v = row[k] * r;
        dst[k] = __float2bfloat16(v);
        dst8[k] = (uint8_t)__nv_cvt_float_to_fp8(v * FP8_SCALE, __NV_SATFINITE, __NV_E4M3);
    }
}

// ---------------- 2) label histogram ----------------
__global__ void hist_kernel(const int* __restrict__ labels) {
    __shared__ int h[NLAB];
    if (threadIdx.x < NLAB) h[threadIdx.x] = 0;
    __syncthreads();
    for (int i = threadIdx.x; i < B_ROWS; i += blockDim.x) atomicAdd(&h[labels[i]], 1);
    __syncthreads();
    if (threadIdx.x < NLAB) g_cnt[threadIdx.x] = h[threadIdx.x];
}

// ---------------- 3) logits + per-row CE (warp per row) ----------------
__global__ __launch_bounds__(256)
void logits_kernel(const float* __restrict__ pooled,
                   const float* __restrict__ W,
                   const float* __restrict__ bias,
                   const int* __restrict__ labels,
                   float* __restrict__ out_logits) {
    int row = blockIdx.x * 8 + (threadIdx.x >> 5);
    int lane = threadIdx.x & 31;
    const float* x = pooled + (size_t)row * DDIM;
    float xr[24];
#pragma unroll
    for (int j = 0; j < 24; j++) xr[j] = x[lane + j * 32];
    float lg[NLAB];
#pragma unroll
    for (int l = 0; l < NLAB; l++) {
        const float* wr = W + (size_t)l * DDIM;
        float dot = 0.f;
#pragma unroll
        for (int j = 0; j < 24; j++) dot += xr[j] * wr[lane + j * 32];
#pragma unroll
        for (int off = 16; off > 0; off >>= 1) dot += __shfl_xor_sync(0xffffffffu, dot, off);
        lg[l] = dot + bias[l];
    }
    if (lane == 0) {
        float mx = lg[0];
#pragma unroll
        for (int c = 1; c < NLAB; c++) mx = fmaxf(mx, lg[c]);
        float se = 0.f;
#pragma unroll
        for (int c = 0; c < NLAB; c++) { se += expf(lg[c] - mx); out_logits[(size_t)row * NLAB + c] = lg[c]; }
        g_ce[row] = mx + logf(se) - lg[labels[row]];
    }
}

// ---------------- 4) per-label embedding sums ----------------
__global__ __launch_bounds__(256)
void zsum_kernel(const int* __restrict__ labels) {
    __shared__ int sLab[ZROWS];
    const int t = threadIdx.x;
    if (t < ZROWS) sLab[t] = labels[blockIdx.x * ZROWS + t];
    __syncthreads();

    float acc[NLAB][3];
#pragma unroll
    for (int l = 0; l < NLAB; l++)
#pragma unroll
        for (int c = 0; c < 3; c++) acc[l][c] = 0.f;

    const int r0 = blockIdx.x * ZROWS;
#pragma unroll 4
    for (int rr = 0; rr < ZROWS; rr++) {
        const int lab = sLab[rr];
        const __nv_bfloat16* row = g_en + (size_t)(r0 + rr) * DDIM;
#pragma unroll
        for (int c = 0; c < 3; c++) {
            float v = __bfloat162float(row[t + c * 256]);
#pragma unroll
            for (int l = 0; l < NLAB; l++)
                acc[l][c] += (l == lab) ? v : 0.f;
        }
    }
#pragma unroll
    for (int l = 0; l < NLAB; l++)
#pragma unroll
        for (int c = 0; c < 3; c++)
            g_Zpart[blockIdx.x][l * DDIM + t + c * 256] = acc[l][c];
}

__global__ void zred_kernel() {
    int i = blockIdx.x * 256 + threadIdx.x;
    if (i < NLAB * DDIM) {
        float s = 0.f;
#pragma unroll 8
        for (int b = 0; b < ZBLK; b++) s += g_Zpart[b][i];
        g_Z[i] = s;
    }
}

// ---------------- 5) pos_r = (en_r . Z[lab_r] - ||en_r||^2) / T ----------------
__global__ void pos_kernel(const int* __restrict__ labels) {
    int row = blockIdx.x * 8 + (threadIdx.x >> 5);
    int lane = threadIdx.x & 31;
    int l = labels[row];
    const __nv_bfloat16* e = g_en + (size_t)row * DDIM;
    const float* z = g_Z + l * DDIM;
    float dot = 0.f, d = 0.f;
#pragma unroll
    for (int k = lane; k < DDIM; k += 32) {
        float v = __bfloat162float(e[k]);
        dot += v * z[k];
        d += v * v;
    }
#pragma unroll
    for (int off = 16; off > 0; off >>= 1) {
        dot += __shfl_xor_sync(0xffffffffu, dot, off);
        d   += __shfl_xor_sync(0xffffffffu, d, off);
    }
    if (lane == 0) g_pos[row] = (dot - d) * (1.0f / TEMP);
}

// ---------------- 6) fp8 upper-tri tiles: S GEMM + exp row/col partial sums ----------------
__global__ __launch_bounds__(256, 2)
void contrast_kernel() {
    __shared__ __align__(16) char sbuf[NSTAGE][256 * PADB];  // 61440 B

    const int tid = threadIdx.x;
    const int lane = tid & 31;
    const int wid = tid >> 5;
    const int wm = wid >> 1;  // 0..3 (rows wm*32)
    const int wn = wid & 1;   // 0..1 (cols wn*64)

    // tile index -> (I, J), I <= J
    int t = blockIdx.x;
    int I = (int)(64.5f - sqrtf(64.5f * 64.5f - 2.0f * (float)t));
    while ((I + 1) * NT - ((I + 1) * I) / 2 <= t) ++I;
    while (I * NT - (I * (I - 1)) / 2 > t) --I;
    const int J = I + (t - (I * NT - (I * (I - 1)) / 2));
    const int rowBase = I * BM;
    const int colBase = J * BN;

    float acc[2][8][4];
#pragma unroll
    for (int mf = 0; mf < 2; mf++)
#pragma unroll
        for (int nf = 0; nf < 8; nf++)
#pragma unroll
            for (int e = 0; e < 4; e++) acc[mf][nf][e] = 0.f;

    // ---- prologue: issue stages 0,1 ----
#pragma unroll
    for (int p = 0; p < 2; p++) {
        const uint8_t* base = g_en8 + p * BKB;
#pragma unroll
        for (int it = 0; it < 4; it++) {
            int idx = tid + 256 * it;
            int r = idx >> 2;             // 0..255 (0-127 A, 128-255 B)
            int qb = (idx & 3) * 16;      // byte offset within 64B row chunk
            int gr = (r < BM) ? (rowBase + r) : (colBase + r - BM);
            cp16(&sbuf[p][r * PADB + qb], base + (size_t)gr * DDIM + qb);
        }
        CP_COMMIT();
    }

    // ---- mainloop: 12 k-chunks, 3-stage cp.async pipeline ----
#pragma unroll 1
    for (int kc = 0; kc < NKC; kc++) {
        if (kc + 2 < NKC) {
            const uint8_t* base = g_en8 + (kc + 2) * BKB;
            char* dbuf = sbuf[(kc + 2) % NSTAGE];
#pragma unroll
            for (int it = 0; it < 4; it++) {
                int idx = tid + 256 * it;
                int r = idx >> 2;
                int qb = (idx & 3) * 16;
                int gr = (r < BM) ? (rowBase + r) : (colBase + r - BM);
                cp16(&dbuf[r * PADB + qb], base + (size_t)gr * DDIM + qb);
            }
            CP_COMMIT();
            asm volatile("cp.async.wait_group 2;\n" ::: "memory");
        } else if (kc + 2 == NKC) {
            asm volatile("cp.async.wait_group 1;\n" ::: "memory");
        } else {
            asm volatile("cp.async.wait_group 0;\n" ::: "memory");
        }
        __syncthreads();

        const char* sA = sbuf[kc % NSTAGE];
        const char* sB = sA + 128 * PADB;
#pragma unroll
        for (int ks = 0; ks < 2; ks++) {     // 2 x (16 b16 units = 32 fp8 k)
            uint32_t a[2][4];
#pragma unroll
            for (int mf = 0; mf < 2; mf++) {
                int row = wm * 32 + mf * 16 + (lane & 15);
                int kcol = ks * 16 + (lane >> 4) * 8;          // b16 units
                ldsm_x4(a[mf], (const __nv_bfloat16*)(sA + row * PADB) + kcol);
            }
            uint32_t bb[8][2];
#pragma unroll
            for (int nf2 = 0; nf2 < 4; nf2++) {
                int mi = lane >> 3;
                int rrow = wn * 64 + nf2 * 16 + ((mi >> 1) << 3) + (lane & 7);
                int kk = ks * 16 + ((mi & 1) << 3);            // b16 units
                ldsm_x4(&bb[nf2 * 2][0], (const __nv_bfloat16*)(sB + rrow * PADB) + kk);
            }
#pragma unroll
            for (int mf = 0; mf < 2; mf++)
#pragma unroll
                for (int nf = 0; nf < 8; nf++)
                    mma_fp8(acc[mf][nf], a[mf], bb[nf]);
        }
        __syncthreads();
    }

    // ---- epilogue: exp + row/col partials (S = acc / 256; s/T bounded) ----
    const float invT = (1.0f / TEMP) / (FP8_SCALE * FP8_SCALE);
    float rs[4] = {0.f, 0.f, 0.f, 0.f};
    float cs[16];
#pragma unroll
    for (int j = 0; j < 16; j++) cs[j] = 0.f;

    if (I != J) {
#pragma unroll
        for (int mf = 0; mf < 2; mf++)
#pragma unroll
            for (int nf = 0; nf < 8; nf++) {
                float e0 = __expf(acc[mf][nf][0] * invT);
                float e1 = __expf(acc[mf][nf][1] * invT);
                float e2 = __expf(acc[mf][nf][2] * invT);
                float e3 = __expf(acc[mf][nf][3] * invT);
                rs[mf * 2 + 0] += e0 + e1;
                rs[mf * 2 + 1] += e2 + e3;
                cs[nf * 2 + 0] += e0 + e2;
                cs[nf * 2 + 1] += e1 + e3;
            }
    } else {
        const int r0 = wm * 32 + (lane >> 2);
        const int c0 = wn * 64 + (lane & 3) * 2;
#pragma unroll
        for (int mf = 0; mf < 2; mf++)
#pragma unroll
            for (int nf = 0; nf < 8; nf++) {
                int rr = r0 + mf * 16, cc = c0 + nf * 8;
                float e0 = (cc     > rr    ) ? __expf(acc[mf][nf][0] * invT) : 0.f;
                float e1 = (cc + 1 > rr    ) ? __expf(acc[mf][nf][1] * invT) : 0.f;
                float e2 = (cc     > rr + 8) ? __expf(acc[mf][nf][2] * invT) : 0.f;
                float e3 = (cc + 1 > rr + 8) ? __expf(acc[mf][nf][3] * invT) : 0.f;
                rs[mf * 2 + 0] += e0 + e1;
                rs[mf * 2 + 1] += e2 + e3;
                cs[nf * 2 + 0] += e0 + e2;
                cs[nf * 2 + 1] += e1 + e3;
            }
    }

#pragma unroll
    for (int j = 0; j < 4; j++) {
        rs[j] += __shfl_xor_sync(0xffffffffu, rs[j], 1);
        rs[j] += __shfl_xor_sync(0xffffffffu, rs[j], 2);
    }
#pragma unroll
    for (int j = 0; j < 16; j++) {
        cs[j] += __shfl_xor_sync(0xffffffffu, cs[j], 4);
        cs[j] += __shfl_xor_sync(0xffffffffu, cs[j], 8);
        cs[j] += __shfl_xor_sync(0xffffffffu, cs[j], 16);
    }

    float* srow = (float*)sbuf;        // [2][128]
    float* scol = srow + 2 * 128;      // [4][128]
    if ((lane & 3) == 0) {
#pragma unroll
        for (int j = 0; j < 4; j++) {
            int row = wm * 32 + (j >> 1) * 16 + (lane >> 2) + (j & 1) * 8;
            srow[wn * 128 + row] = rs[j];
        }
    }
    if (lane < 4) {
#pragma unroll
        for (int j = 0; j < 16; j++) {
            int col = wn * 64 + (j >> 1) * 8 + lane * 2 + (j & 1);
            scol[wm * 128 + col] = cs[j];
        }
    }
    __syncthreads();

    if (tid < 128) {
        float rsum = srow[tid] + srow[128 + tid];
        float csum = scol[tid] + scol[128 + tid] + scol[256 + tid] + scol[384 + tid];
        if (I == J) {
            g_part[I][rowBase + tid] = rsum + csum;
        } else {
            g_part[J][rowBase + tid] = rsum;   // rows of block I, slot J
            g_part[I][colBase + tid] = csum;   // rows of block J, slot I
        }
    }
}

// ---------------- 7) final loss ----------------
__global__ void finalize_kernel(const int* __restrict__ labels, float* __restrict__ d_out) {
    __shared__ float sc[256], se[256];
    int t = threadIdx.x;
    float c = 0.f, e = 0.f;
    for (int r = t; r < B_ROWS; r += 256) {
        float es = 0.f;
#pragma unroll 8
        for (int j = 0; j < NT; j++) es += g_part[j][r];
        float lse = logf(es);
        int ni = g_cnt[labels[r]] - 1;
        float pa = (ni > 0) ? (lse - g_pos[r] / (float)ni) : 0.f;
        c += pa;
        e += g_ce[r];
    }
    sc[t] = c; se[t] = e;
    __syncthreads();
    for (int s = 128; s > 0; s >>= 1) {
        if (t < s) { sc[t] += sc[t + s]; se[t] += se[t + s]; }
        __syncthreads();
    }
    if (t == 0) d_out[0] = LAM * sc[0] + (1.0f - LAM) * (se[0] / (float)B_ROWS);
}

// ---------------- launch ----------------
extern "C" void kernel_launch(void* const* d_in, const int* in_sizes, int n_in,
                              void* d_out, int out_size) {
    const float* cls    = (const float*)d_in[0];
    const float* pooled = (const float*)d_in[1];
    const int*   labels = (const int*)d_in[2];
    const float* W      = (const float*)d_in[3];
    const float* bias   = (const float*)d_in[4];
    float* out = (float*)d_out;   // [0] = loss, [1..] = logits

    norm_kernel<<<B_ROWS / 8, 256>>>(cls);
    hist_kernel<<<1, 256>>>(labels);
    logits_kernel<<<B_ROWS / 8, 256>>>(pooled, W, bias, labels, out + 1);
    zsum_kernel<<<ZBLK, 256>>>(labels);
    zred_kernel<<<(NLAB * DDIM + 255) / 256, 256>>>();
    pos_kernel<<<B_ROWS / 8, 256>>>(labels);
    contrast_kernel<<<NTILES, 256>>>();
    finalize_kernel<<<1, 256>>>(labels, out);
}